// round 8
// baseline (speedup 1.0000x reference)
#include <cuda_runtime.h>
#include <cstdint>

#define IN_DIM 128
#define OUT_DIM 128
#define MAX_NODES 50000
#define MAX_EDGES 800000

// Static scratch (no allocations allowed)
__device__ int   g_degcnt[MAX_NODES];     // count of col==i
__device__ int   g_rowcnt[MAX_NODES];     // count of row==i
__device__ int   g_rowfill[MAX_NODES];    // fill cursor per row
__device__ int   g_rowptr[MAX_NODES + 1]; // CSR offsets
__device__ int   g_cs[MAX_EDGES];         // CSR col indices (bucketed by row)
__device__ float g_dinv[MAX_NODES];
__device__ float g_h[(size_t)MAX_NODES * OUT_DIM];

// ---------------------------------------------------------------------------
// Init: zero counters (must re-run every launch — graph replays)
// ---------------------------------------------------------------------------
__global__ void k_init(int n) {
    int i = blockIdx.x * blockDim.x + threadIdx.x;
    if (i < n) {
        g_degcnt[i]  = 0;
        g_rowcnt[i]  = 0;
        g_rowfill[i] = 0;
    }
}

// ---------------------------------------------------------------------------
// Histogram: per-row counts (CSR) and per-col counts (degree)
// edge_index is int32 (JAX silently downcasts int64 without x64 mode)
// ---------------------------------------------------------------------------
__global__ void k_count(const int* __restrict__ row,
                        const int* __restrict__ col, int E) {
    int i = blockIdx.x * blockDim.x + threadIdx.x;
    if (i < E) {
        atomicAdd(&g_rowcnt[row[i]], 1);
        atomicAdd(&g_degcnt[col[i]], 1);
    }
}

// ---------------------------------------------------------------------------
// Exclusive scan of g_rowcnt -> g_rowptr  (single block, 1024 threads)
// ---------------------------------------------------------------------------
__global__ void __launch_bounds__(1024) k_scan(int n) {
    __shared__ int sdata[1024];
    __shared__ int s_carry;
    int tid = threadIdx.x;
    if (tid == 0) { s_carry = 0; g_rowptr[0] = 0; }
    __syncthreads();

    for (int base = 0; base < n; base += 1024) {
        int i = base + tid;
        int v = (i < n) ? g_rowcnt[i] : 0;
        sdata[tid] = v;
        __syncthreads();
#pragma unroll
        for (int off = 1; off < 1024; off <<= 1) {
            int t = (tid >= off) ? sdata[tid - off] : 0;
            __syncthreads();
            sdata[tid] += t;
            __syncthreads();
        }
        if (i < n) g_rowptr[i + 1] = s_carry + sdata[tid];
        __syncthreads();
        if (tid == 0) s_carry += sdata[1023];
        __syncthreads();
    }
}

// ---------------------------------------------------------------------------
// dinv = rsqrt(1 + degcnt)   (self-loop included)
// ---------------------------------------------------------------------------
__global__ void k_dinv(int n) {
    int i = blockIdx.x * blockDim.x + threadIdx.x;
    if (i < n) g_dinv[i] = rsqrtf(1.0f + (float)g_degcnt[i]);
}

// ---------------------------------------------------------------------------
// Fill CSR: g_cs[rowptr[r] + slot] = col
// ---------------------------------------------------------------------------
__global__ void k_fill(const int* __restrict__ row,
                       const int* __restrict__ col, int E) {
    int i = blockIdx.x * blockDim.x + threadIdx.x;
    if (i < E) {
        int r = row[i];
        int slot = atomicAdd(&g_rowfill[r], 1);
        g_cs[g_rowptr[r] + slot] = col[i];
    }
}

// ---------------------------------------------------------------------------
// GEMM: h[m][n] = sum_k x[m][k] * W[n][k]
// BM=64, BN=128, BK=16; 256 threads; 4x8 thread tile.
// Epilogue: g_h = h;  out = dinv[m]^2 * h   (self-loop term init)
// ---------------------------------------------------------------------------
__global__ void __launch_bounds__(256) k_gemm(const float* __restrict__ x,
                                              const float* __restrict__ W,
                                              float* __restrict__ out,
                                              int n_nodes) {
    __shared__ float As[16][64];
    __shared__ float Bs[16][128];

    const int tid = threadIdx.x;
    const int bm  = blockIdx.x * 64;
    const int tx  = tid & 15;
    const int ty  = tid >> 4;

    float acc[4][8];
#pragma unroll
    for (int i = 0; i < 4; i++)
#pragma unroll
        for (int j = 0; j < 8; j++) acc[i][j] = 0.0f;

    const int lm = tid >> 2;
    const int lk = (tid & 3) * 4;
    const int wn = tid >> 1;
    const int wk = (tid & 1) * 8;

    for (int kc = 0; kc < IN_DIM; kc += 16) {
        float4 xv = make_float4(0.f, 0.f, 0.f, 0.f);
        int m = bm + lm;
        if (m < n_nodes)
            xv = *(const float4*)(x + (size_t)m * IN_DIM + kc + lk);
        As[lk + 0][lm] = xv.x;
        As[lk + 1][lm] = xv.y;
        As[lk + 2][lm] = xv.z;
        As[lk + 3][lm] = xv.w;

        float4 w0 = *(const float4*)(W + (size_t)wn * IN_DIM + kc + wk);
        float4 w1 = *(const float4*)(W + (size_t)wn * IN_DIM + kc + wk + 4);
        Bs[wk + 0][wn] = w0.x;
        Bs[wk + 1][wn] = w0.y;
        Bs[wk + 2][wn] = w0.z;
        Bs[wk + 3][wn] = w0.w;
        Bs[wk + 4][wn] = w1.x;
        Bs[wk + 5][wn] = w1.y;
        Bs[wk + 6][wn] = w1.z;
        Bs[wk + 7][wn] = w1.w;
        __syncthreads();

#pragma unroll
        for (int k = 0; k < 16; k++) {
            float4 a  = ((const float4*)As[k])[ty];
            float4 b0 = ((const float4*)Bs[k])[tx * 2];
            float4 b1 = ((const float4*)Bs[k])[tx * 2 + 1];
            float av[4] = {a.x, a.y, a.z, a.w};
            float bv[8] = {b0.x, b0.y, b0.z, b0.w, b1.x, b1.y, b1.z, b1.w};
#pragma unroll
            for (int i = 0; i < 4; i++)
#pragma unroll
                for (int j = 0; j < 8; j++) acc[i][j] += av[i] * bv[j];
        }
        __syncthreads();
    }

#pragma unroll
    for (int i = 0; i < 4; i++) {
        int m = bm + ty * 4 + i;
        if (m >= n_nodes) continue;
        float di  = g_dinv[m];
        float di2 = di * di;
        float4 h0 = make_float4(acc[i][0], acc[i][1], acc[i][2], acc[i][3]);
        float4 h1 = make_float4(acc[i][4], acc[i][5], acc[i][6], acc[i][7]);
        float4 o0 = make_float4(h0.x * di2, h0.y * di2, h0.z * di2, h0.w * di2);
        float4 o1 = make_float4(h1.x * di2, h1.y * di2, h1.z * di2, h1.w * di2);
        size_t base = (size_t)m * OUT_DIM + tx * 8;
        *(float4*)(g_h + base)     = h0;
        *(float4*)(g_h + base + 4) = h1;
        *(float4*)(out + base)     = o0;
        *(float4*)(out + base + 4) = o1;
    }
}

// ---------------------------------------------------------------------------
// Aggregate: one warp per node (owner-computes, no atomics).
// out[i] = relu( out[i] + sum_{e in row i} dinv[i]*dinv[col] * h[col] )
// ---------------------------------------------------------------------------
__global__ void __launch_bounds__(256) k_agg(float* __restrict__ out, int n) {
    int w    = (blockIdx.x * blockDim.x + threadIdx.x) >> 5;
    int lane = threadIdx.x & 31;
    if (w >= n) return;

    int s = g_rowptr[w];
    int e = g_rowptr[w + 1];
    float di = g_dinv[w];

    float* op = out + (size_t)w * OUT_DIM + lane * 4;
    float4 acc = *(float4*)op;  // self-loop term from GEMM epilogue

    int j = s;
    for (; j + 1 < e; j += 2) {
        int c0 = g_cs[j];
        int c1 = g_cs[j + 1];
        float w0 = di * g_dinv[c0];
        float w1 = di * g_dinv[c1];
        float4 h0 = *(const float4*)(g_h + (size_t)c0 * OUT_DIM + lane * 4);
        float4 h1 = *(const float4*)(g_h + (size_t)c1 * OUT_DIM + lane * 4);
        acc.x += w0 * h0.x + w1 * h1.x;
        acc.y += w0 * h0.y + w1 * h1.y;
        acc.z += w0 * h0.z + w1 * h1.z;
        acc.w += w0 * h0.w + w1 * h1.w;
    }
    if (j < e) {
        int c = g_cs[j];
        float wt = di * g_dinv[c];
        float4 hv = *(const float4*)(g_h + (size_t)c * OUT_DIM + lane * 4);
        acc.x += wt * hv.x;
        acc.y += wt * hv.y;
        acc.z += wt * hv.z;
        acc.w += wt * hv.w;
    }

    acc.x = fmaxf(acc.x, 0.f);
    acc.y = fmaxf(acc.y, 0.f);
    acc.z = fmaxf(acc.z, 0.f);
    acc.w = fmaxf(acc.w, 0.f);
    *(float4*)op = acc;
}

// ---------------------------------------------------------------------------
extern "C" void kernel_launch(void* const* d_in, const int* in_sizes, int n_in,
                              void* d_out, int out_size) {
    const float* x  = (const float*)d_in[0];
    const float* W  = (const float*)d_in[1];
    const int*   ei = (const int*)d_in[2];   // int32! (JAX x64 disabled)
    float* out = (float*)d_out;

    const int n_nodes = in_sizes[0] / IN_DIM;
    const int E       = in_sizes[2] / 2;
    const int* row = ei;
    const int* col = ei + E;

    k_init <<<(n_nodes + 255) / 256, 256>>>(n_nodes);
    k_count<<<(E + 255) / 256, 256>>>(row, col, E);
    k_scan <<<1, 1024>>>(n_nodes);
    k_dinv <<<(n_nodes + 255) / 256, 256>>>(n_nodes);
    k_fill <<<(E + 255) / 256, 256>>>(row, col, E);
    k_gemm <<<(n_nodes + 63) / 64, 256>>>(x, W, out, n_nodes);

    int warps_per_block = 256 / 32;
    int agg_blocks = (n_nodes + warps_per_block - 1) / warps_per_block;
    k_agg  <<<agg_blocks, 256>>>(out, n_nodes);
}

// round 9
// speedup vs baseline: 1.0653x; 1.0653x over previous
#include <cuda_runtime.h>
#include <cstdint>

#define IN_DIM 128
#define OUT_DIM 128
#define MAX_NODES 50000
#define MAX_EDGES 800000

// Static scratch (no allocations allowed)
__device__ int   g_degcnt[MAX_NODES];     // count of col==i
__device__ int   g_rowcnt[MAX_NODES];     // count of row==i
__device__ int   g_rowfill[MAX_NODES];    // fill cursor per row
__device__ int   g_rowptr[MAX_NODES + 1]; // CSR offsets
__device__ int   g_cs[MAX_EDGES];         // CSR col indices (bucketed by row)
__device__ float g_dinv[MAX_NODES];
__device__ float g_h[(size_t)MAX_NODES * OUT_DIM];

// ---------------------------------------------------------------------------
// Init: zero counters (graph replays -> must rerun every launch)
// ---------------------------------------------------------------------------
__global__ void k_init(int n) {
    int i = blockIdx.x * blockDim.x + threadIdx.x;
    if (i < n) {
        g_degcnt[i]  = 0;
        g_rowcnt[i]  = 0;
        g_rowfill[i] = 0;
    }
}

// ---------------------------------------------------------------------------
// Histogram: per-row counts (CSR) and per-col counts (degree). int32 indices.
// ---------------------------------------------------------------------------
__global__ void k_count(const int* __restrict__ row,
                        const int* __restrict__ col, int E) {
    int i = blockIdx.x * blockDim.x + threadIdx.x;
    if (i < E) {
        atomicAdd(&g_rowcnt[row[i]], 1);
        atomicAdd(&g_degcnt[col[i]], 1);
    }
}

// ---------------------------------------------------------------------------
// Exclusive scan of g_rowcnt -> g_rowptr, single block, shuffle-based.
// Thread t serially owns chunk [t*C, (t+1)*C); one block-scan of 1024 sums.
// Fused: dinv = rsqrt(1 + degcnt)  (striped, coalesced, independent work)
// ---------------------------------------------------------------------------
__global__ void __launch_bounds__(1024) k_scan_dinv(int n) {
    __shared__ int warp_sums[32];
    const int tid   = threadIdx.x;
    const int lane  = tid & 31;
    const int wid   = tid >> 5;
    const int CHUNK = (n + 1023) / 1024;
    const int s = tid * CHUNK;
    const int e = (s + CHUNK < n) ? s + CHUNK : n;

    // phase 1: local chunk sum
    int sum = 0;
    for (int i = s; i < e; i++) sum += g_rowcnt[i];

    // block inclusive scan of per-thread sums (warp shuffles)
    int v = sum;
#pragma unroll
    for (int o = 1; o < 32; o <<= 1) {
        int t = __shfl_up_sync(0xFFFFFFFFu, v, o);
        if (lane >= o) v += t;
    }
    if (lane == 31) warp_sums[wid] = v;
    __syncthreads();
    if (wid == 0) {
        int wv = warp_sums[lane];
#pragma unroll
        for (int o = 1; o < 32; o <<= 1) {
            int t = __shfl_up_sync(0xFFFFFFFFu, wv, o);
            if (lane >= o) wv += t;
        }
        warp_sums[lane] = wv;
    }
    __syncthreads();
    int excl = v - sum + (wid > 0 ? warp_sums[wid - 1] : 0);

    // phase 2: write rowptr prefix for my chunk
    if (tid == 0) g_rowptr[0] = 0;
    int run = excl;
    for (int i = s; i < e; i++) {
        run += g_rowcnt[i];
        g_rowptr[i + 1] = run;
    }

    // fused dinv (coalesced striped)
    for (int i = tid; i < n; i += 1024)
        g_dinv[i] = rsqrtf(1.0f + (float)g_degcnt[i]);
}

// ---------------------------------------------------------------------------
// Fill CSR: g_cs[rowptr[r] + slot] = col
// ---------------------------------------------------------------------------
__global__ void k_fill(const int* __restrict__ row,
                       const int* __restrict__ col, int E) {
    int i = blockIdx.x * blockDim.x + threadIdx.x;
    if (i < E) {
        int r = row[i];
        int slot = atomicAdd(&g_rowfill[r], 1);
        g_cs[g_rowptr[r] + slot] = col[i];
    }
}

// ---------------------------------------------------------------------------
// GEMM: h[m][n] = sum_k x[m][k] * W[n][k]
// BM=64, BN=128, BK=16; 256 threads; 4x8 thread tile.
// Epilogue: g_h = h;  out = dinv[m]^2 * h   (self-loop term init)
// ---------------------------------------------------------------------------
__global__ void __launch_bounds__(256) k_gemm(const float* __restrict__ x,
                                              const float* __restrict__ W,
                                              float* __restrict__ out,
                                              int n_nodes) {
    __shared__ float As[16][64];
    __shared__ float Bs[16][128];

    const int tid = threadIdx.x;
    const int bm  = blockIdx.x * 64;
    const int tx  = tid & 15;
    const int ty  = tid >> 4;

    float acc[4][8];
#pragma unroll
    for (int i = 0; i < 4; i++)
#pragma unroll
        for (int j = 0; j < 8; j++) acc[i][j] = 0.0f;

    const int lm = tid >> 2;
    const int lk = (tid & 3) * 4;
    const int wn = tid >> 1;
    const int wk = (tid & 1) * 8;

    for (int kc = 0; kc < IN_DIM; kc += 16) {
        float4 xv = make_float4(0.f, 0.f, 0.f, 0.f);
        int m = bm + lm;
        if (m < n_nodes)
            xv = *(const float4*)(x + (size_t)m * IN_DIM + kc + lk);
        As[lk + 0][lm] = xv.x;
        As[lk + 1][lm] = xv.y;
        As[lk + 2][lm] = xv.z;
        As[lk + 3][lm] = xv.w;

        float4 w0 = *(const float4*)(W + (size_t)wn * IN_DIM + kc + wk);
        float4 w1 = *(const float4*)(W + (size_t)wn * IN_DIM + kc + wk + 4);
        Bs[wk + 0][wn] = w0.x;
        Bs[wk + 1][wn] = w0.y;
        Bs[wk + 2][wn] = w0.z;
        Bs[wk + 3][wn] = w0.w;
        Bs[wk + 4][wn] = w1.x;
        Bs[wk + 5][wn] = w1.y;
        Bs[wk + 6][wn] = w1.z;
        Bs[wk + 7][wn] = w1.w;
        __syncthreads();

#pragma unroll
        for (int k = 0; k < 16; k++) {
            float4 a  = ((const float4*)As[k])[ty];
            float4 b0 = ((const float4*)Bs[k])[tx * 2];
            float4 b1 = ((const float4*)Bs[k])[tx * 2 + 1];
            float av[4] = {a.x, a.y, a.z, a.w};
            float bv[8] = {b0.x, b0.y, b0.z, b0.w, b1.x, b1.y, b1.z, b1.w};
#pragma unroll
            for (int i = 0; i < 4; i++)
#pragma unroll
                for (int j = 0; j < 8; j++) acc[i][j] += av[i] * bv[j];
        }
        __syncthreads();
    }

#pragma unroll
    for (int i = 0; i < 4; i++) {
        int m = bm + ty * 4 + i;
        if (m >= n_nodes) continue;
        float di  = g_dinv[m];
        float di2 = di * di;
        float4 h0 = make_float4(acc[i][0], acc[i][1], acc[i][2], acc[i][3]);
        float4 h1 = make_float4(acc[i][4], acc[i][5], acc[i][6], acc[i][7]);
        float4 o0 = make_float4(h0.x * di2, h0.y * di2, h0.z * di2, h0.w * di2);
        float4 o1 = make_float4(h1.x * di2, h1.y * di2, h1.z * di2, h1.w * di2);
        size_t base = (size_t)m * OUT_DIM + tx * 8;
        *(float4*)(g_h + base)     = h0;
        *(float4*)(g_h + base + 4) = h1;
        *(float4*)(out + base)     = o0;
        *(float4*)(out + base + 4) = o1;
    }
}

// ---------------------------------------------------------------------------
// Aggregate: one warp per node (owner-computes, no atomics), 4-edge unroll
// out[i] = relu( out[i] + sum_{e in row i} dinv[i]*dinv[col] * h[col] )
// ---------------------------------------------------------------------------
__global__ void __launch_bounds__(256) k_agg(float* __restrict__ out, int n) {
    int w    = (blockIdx.x * blockDim.x + threadIdx.x) >> 5;
    int lane = threadIdx.x & 31;
    if (w >= n) return;

    int s = g_rowptr[w];
    int e = g_rowptr[w + 1];
    float di = g_dinv[w];

    float* op = out + (size_t)w * OUT_DIM + lane * 4;
    float4 acc = *(float4*)op;  // self-loop term from GEMM epilogue

    int j = s;
    for (; j + 3 < e; j += 4) {
        int c0 = g_cs[j];
        int c1 = g_cs[j + 1];
        int c2 = g_cs[j + 2];
        int c3 = g_cs[j + 3];
        float w0 = di * g_dinv[c0];
        float w1 = di * g_dinv[c1];
        float w2 = di * g_dinv[c2];
        float w3 = di * g_dinv[c3];
        float4 h0 = *(const float4*)(g_h + (size_t)c0 * OUT_DIM + lane * 4);
        float4 h1 = *(const float4*)(g_h + (size_t)c1 * OUT_DIM + lane * 4);
        float4 h2 = *(const float4*)(g_h + (size_t)c2 * OUT_DIM + lane * 4);
        float4 h3 = *(const float4*)(g_h + (size_t)c3 * OUT_DIM + lane * 4);
        acc.x += w0 * h0.x + w1 * h1.x + w2 * h2.x + w3 * h3.x;
        acc.y += w0 * h0.y + w1 * h1.y + w2 * h2.y + w3 * h3.y;
        acc.z += w0 * h0.z + w1 * h1.z + w2 * h2.z + w3 * h3.z;
        acc.w += w0 * h0.w + w1 * h1.w + w2 * h2.w + w3 * h3.w;
    }
    for (; j < e; j++) {
        int c = g_cs[j];
        float wt = di * g_dinv[c];
        float4 hv = *(const float4*)(g_h + (size_t)c * OUT_DIM + lane * 4);
        acc.x += wt * hv.x;
        acc.y += wt * hv.y;
        acc.z += wt * hv.z;
        acc.w += wt * hv.w;
    }

    acc.x = fmaxf(acc.x, 0.f);
    acc.y = fmaxf(acc.y, 0.f);
    acc.z = fmaxf(acc.z, 0.f);
    acc.w = fmaxf(acc.w, 0.f);
    *(float4*)op = acc;
}

// ---------------------------------------------------------------------------
extern "C" void kernel_launch(void* const* d_in, const int* in_sizes, int n_in,
                              void* d_out, int out_size) {
    const float* x  = (const float*)d_in[0];
    const float* W  = (const float*)d_in[1];
    const int*   ei = (const int*)d_in[2];   // int32 (JAX x64 disabled)
    float* out = (float*)d_out;

    const int n_nodes = in_sizes[0] / IN_DIM;
    const int E       = in_sizes[2] / 2;
    const int* row = ei;
    const int* col = ei + E;

    k_init     <<<(n_nodes + 255) / 256, 256>>>(n_nodes);
    k_count    <<<(E + 255) / 256, 256>>>(row, col, E);
    k_scan_dinv<<<1, 1024>>>(n_nodes);
    k_fill     <<<(E + 255) / 256, 256>>>(row, col, E);
    k_gemm     <<<(n_nodes + 63) / 64, 256>>>(x, W, out, n_nodes);

    int warps_per_block = 256 / 32;
    int agg_blocks = (n_nodes + warps_per_block - 1) / warps_per_block;
    k_agg      <<<agg_blocks, 256>>>(out, n_nodes);
}